// round 2
// baseline (speedup 1.0000x reference)
#include <cuda_runtime.h>

#define CIN 64
#define COUT 64
#define HW 32
#define KTOT 576
#define KT 192
#define NT 3
#define XS_STRIDE 196   // 192 data + 4 pad; 196 % 32 == 4 -> conflict-free, 784B row is 16B-aligned

// x transposed to [ci][h][w][b] (batch innermost, contiguous 128B per (ci,h,w))
__device__ float g_xt[CIN * HW * HW * 32];

__global__ void transpose_x_kernel(const float* __restrict__ x) {
    __shared__ float tile[32][33];
    int cih = blockIdx.x;             // ci*32 + h
    int lane = threadIdx.x & 31;
    int grp  = threadIdx.x >> 5;      // 0..7
    const float* src = x + (size_t)cih * 32;
#pragma unroll
    for (int i = 0; i < 4; ++i) {
        int b = grp + 8 * i;
        tile[b][lane] = src[(size_t)b * 65536 + lane];
    }
    __syncthreads();
    float* dst = g_xt + (size_t)cih * 1024;   // [w][b]
#pragma unroll
    for (int i = 0; i < 4; ++i) {
        int w = grp + 8 * i;
        dst[w * 32 + lane] = tile[lane][w];
    }
}

__global__ __launch_bounds__(128, 5) void local2d_kernel(
    const float* __restrict__ wgt,   // [pos][co][k], k = ci*9+ki*3+kj
    const float* __restrict__ bias,  // [co][pos]
    float* __restrict__ out)         // [b][co][pos]
{
    __shared__ __align__(16) float xs2[32][XS_STRIDE];  // [b][k-local]
    __shared__ int xoffs[KTOT];

    int pos = blockIdx.x;
    int y = pos >> 5, x = pos & 31;
    int tid = threadIdx.x;

    // compute thread mapping: b set = {by, by+8, by+16, by+24}, co set = {cx, cx+16, cx+32, cx+48}
    int by = tid & 7;
    int cx = tid >> 3;    // 0..15

    // staging mapping: b = 8*wq + r, k-local = h + 4*t2
    int r  = tid & 7;
    int h  = (tid >> 3) & 3;
    int wq = tid >> 5;
    int sb = 8 * wq + r;

    // ---- precompute g_xt offsets for all 576 k (once) ----
    for (int k = tid; k < KTOT; k += 128) {
        int ci = k / 9;
        int rr = k - ci * 9;
        int ki = rr / 3;
        int kj = rr - ki * 3;
        int iy = y + ki - 1, ix = x + kj - 1;
        int off = -1;
        if ((unsigned)iy < 32u && (unsigned)ix < 32u)
            off = ((ci * 32 + iy) * 32 + ix) * 32;
        xoffs[k] = off;
    }
    __syncthreads();

    const float* wbase = wgt + (size_t)pos * (COUT * KTOT);
    const float* wrow[4];
#pragma unroll
    for (int j = 0; j < 4; ++j)
        wrow[j] = wbase + (size_t)(cx + 16 * j) * KTOT;

    // acc[i][j]: f32x2 partial sums over (even k, odd k) for (b_i, co_j)
    unsigned long long acc[4][4];
#pragma unroll
    for (int i = 0; i < 4; ++i)
#pragma unroll
        for (int j = 0; j < 4; ++j) acc[i][j] = 0ull;

    for (int t = 0; t < NT; ++t) {
        // ---- stage x tile: [32 b][KT k] (conflict-free STS, sector-aligned LDG) ----
#pragma unroll 4
        for (int t2 = 0; t2 < KT / 4; ++t2) {
            int kl = h + 4 * t2;
            int off = xoffs[t * KT + kl];
            float v = 0.f;
            if (off >= 0) v = g_xt[off + sb];
            xs2[sb][kl] = v;
        }
        __syncthreads();

        // ---- compute: k-pair packed f32x2, weights streamed from gmem ----
        const float* wt = wbase;  // silence unused warning pattern
#pragma unroll 4
        for (int k4 = 0; k4 < KT / 4; ++k4) {
            ulonglong2 xv[4];
#pragma unroll
            for (int i = 0; i < 4; ++i)
                xv[i] = *(const ulonglong2*)&xs2[by + 8 * i][k4 * 4];
            ulonglong2 wv[4];
#pragma unroll
            for (int j = 0; j < 4; ++j)
                wv[j] = *(const ulonglong2*)(wrow[j] + t * KT + k4 * 4);
#pragma unroll
            for (int i = 0; i < 4; ++i)
#pragma unroll
                for (int j = 0; j < 4; ++j) {
                    asm("fma.rn.f32x2 %0, %1, %2, %0;"
                        : "+l"(acc[i][j]) : "l"(xv[i].x), "l"(wv[j].x));
                    asm("fma.rn.f32x2 %0, %1, %2, %0;"
                        : "+l"(acc[i][j]) : "l"(xv[i].y), "l"(wv[j].y));
                }
        }
        __syncthreads();
        (void)wt;
    }

    // ---- epilogue: reduce pair halves, add bias, scatter store ----
#pragma unroll
    for (int j = 0; j < 4; ++j) {
        int co = cx + 16 * j;
        float bv = bias[co * 1024 + pos];
#pragma unroll
        for (int i = 0; i < 4; ++i) {
            int b = by + 8 * i;
            unsigned lo, hi;
            asm("mov.b64 {%0, %1}, %2;" : "=r"(lo), "=r"(hi) : "l"(acc[i][j]));
            out[((size_t)b * COUT + co) * 1024 + pos] =
                __uint_as_float(lo) + __uint_as_float(hi) + bv;
        }
    }
}

extern "C" void kernel_launch(void* const* d_in, const int* in_sizes, int n_in,
                              void* d_out, int out_size) {
    const float* x    = (const float*)d_in[0];
    const float* wgt  = (const float*)d_in[1];
    const float* bias = (const float*)d_in[2];
    float* out = (float*)d_out;

    transpose_x_kernel<<<CIN * HW, 256>>>(x);
    local2d_kernel<<<HW * HW, 128>>>(wgt, bias, out);
}

// round 3
// speedup vs baseline: 1.2086x; 1.2086x over previous
#include <cuda_runtime.h>

#define CIN 64
#define COUT 64
#define HW 32
#define KTOT 576
#define KT 64
#define NT 9
#define RS 68   // smem row stride in floats: 272B, 16B-aligned, bank offset 4/row

// x transposed to [ci][h][w][b] (batch innermost, contiguous 128B per (ci,h,w))
__device__ float g_xt[CIN * HW * HW * 32];

__global__ void transpose_x_kernel(const float* __restrict__ x) {
    __shared__ float tile[32][33];
    int cih = blockIdx.x;             // ci*32 + h
    int lane = threadIdx.x & 31;
    int grp  = threadIdx.x >> 5;      // 0..7
    const float* src = x + (size_t)cih * 32;
#pragma unroll
    for (int i = 0; i < 4; ++i) {
        int b = grp + 8 * i;
        tile[b][lane] = src[(size_t)b * 65536 + lane];
    }
    __syncthreads();
    float* dst = g_xt + (size_t)cih * 1024;   // [w][b]
#pragma unroll
    for (int i = 0; i < 4; ++i) {
        int w = grp + 8 * i;
        dst[w * 32 + lane] = tile[lane][w];
    }
}

__global__ __launch_bounds__(128, 5) void local2d_kernel(
    const float* __restrict__ wgt,   // [pos][co][k], k = ci*9+ki*3+kj
    const float* __restrict__ bias,  // [co][pos]
    float* __restrict__ out)         // [b][co][pos]
{
    __shared__ __align__(16) float xs[32 * RS];   // [b][k-local]
    __shared__ __align__(16) float ws[64 * RS];   // [co][k-local]
    __shared__ int xoffs[KTOT];

    int pos = blockIdx.x;
    int y = pos >> 5, x = pos & 31;
    int tid = threadIdx.x;

    // compute mapping: b set = by + 8i, co set = cx + 16j
    int by = tid & 7;
    int cx = tid >> 3;     // 0..15

    // x staging mapping: conflict-free STS (banks 4*blow + kq all distinct per warp)
    int kq   = tid & 3;
    int blow = (tid >> 2) & 7;
    int bst  = blow + 8 * (tid >> 5);

    // ---- precompute g_xt offsets for all 576 k (once per CTA) ----
    for (int k = tid; k < KTOT; k += 128) {
        int ci = k / 9;
        int rr = k - ci * 9;
        int ki = rr / 3;
        int kj = rr - ki * 3;
        int iy = y + ki - 1, ix = x + kj - 1;
        int off = -1;
        if ((unsigned)iy < 32u && (unsigned)ix < 32u)
            off = ((ci * 32 + iy) * 32 + ix) * 32;
        xoffs[k] = off;
    }
    __syncthreads();

    const float* wbase = wgt + (size_t)pos * (COUT * KTOT);

    // acc[i][j]: f32x2 (even-k, odd-k) partial sums for (b_i, co_j)
    unsigned long long acc[4][4];
#pragma unroll
    for (int i = 0; i < 4; ++i)
#pragma unroll
        for (int j = 0; j < 4; ++j) acc[i][j] = 0ull;

    for (int t = 0; t < NT; ++t) {
        // ---- stage weight tile 64co x 64k: coalesced LDG.128 -> STS.128 ----
#pragma unroll
        for (int i = 0; i < 8; ++i) {
            int idx = tid + i * 128;          // 0..1023
            int co = idx >> 4, q = idx & 15;
            float4 v = *(const float4*)(wbase + co * KTOT + t * KT + q * 4);
            *(float4*)&ws[co * RS + q * 4] = v;
        }
        // ---- stage x tile 32b x 64k: conflict-free STS.32 ----
#pragma unroll
        for (int i = 0; i < 16; ++i) {
            int k = kq + 4 * i;
            int off = xoffs[t * KT + k];
            float v = 0.f;
            if (off >= 0) v = g_xt[off + bst];
            xs[bst * RS + k] = v;
        }
        __syncthreads();

        // ---- compute: k-pair packed FFMA2, both operands via LDS.128 ----
#pragma unroll 8
        for (int k4 = 0; k4 < KT / 4; ++k4) {
            ulonglong2 xv[4];
#pragma unroll
            for (int i = 0; i < 4; ++i)
                xv[i] = *(const ulonglong2*)&xs[(by + 8 * i) * RS + k4 * 4];
            ulonglong2 wv[4];
#pragma unroll
            for (int j = 0; j < 4; ++j)
                wv[j] = *(const ulonglong2*)&ws[(cx + 16 * j) * RS + k4 * 4];
#pragma unroll
            for (int i = 0; i < 4; ++i)
#pragma unroll
                for (int j = 0; j < 4; ++j) {
                    asm("fma.rn.f32x2 %0, %1, %2, %0;"
                        : "+l"(acc[i][j]) : "l"(xv[i].x), "l"(wv[j].x));
                    asm("fma.rn.f32x2 %0, %1, %2, %0;"
                        : "+l"(acc[i][j]) : "l"(xv[i].y), "l"(wv[j].y));
                }
        }
        __syncthreads();
    }

    // ---- epilogue: reduce pair halves, add bias, store ----
#pragma unroll
    for (int j = 0; j < 4; ++j) {
        int co = cx + 16 * j;
        float bv = bias[co * 1024 + pos];
#pragma unroll
        for (int i = 0; i < 4; ++i) {
            int b = by + 8 * i;
            unsigned lo, hi;
            asm("mov.b64 {%0, %1}, %2;" : "=r"(lo), "=r"(hi) : "l"(acc[i][j]));
            out[((size_t)b * COUT + co) * 1024 + pos] =
                __uint_as_float(lo) + __uint_as_float(hi) + bv;
        }
    }
}

extern "C" void kernel_launch(void* const* d_in, const int* in_sizes, int n_in,
                              void* d_out, int out_size) {
    const float* x    = (const float*)d_in[0];
    const float* wgt  = (const float*)d_in[1];
    const float* bias = (const float*)d_in[2];
    float* out = (float*)d_out;

    transpose_x_kernel<<<CIN * HW, 256>>>(x);
    local2d_kernel<<<HW * HW, 128>>>(wgt, bias, out);
}

// round 6
// speedup vs baseline: 1.2605x; 1.0429x over previous
#include <cuda_runtime.h>
#include <cstdint>

#define CIN 64
#define COUT 64
#define HW 32
#define KTOT 576
#define KT 32
#define NTILES 18

// x transposed to [ci][h][w][b] (batch innermost -> contiguous 128B rows)
__device__ float g_xt[CIN * HW * HW * 32];

__global__ void transpose_x_kernel(const float* __restrict__ x) {
    __shared__ float tile[32][33];
    int cih = blockIdx.x;
    int lane = threadIdx.x & 31;
    int grp  = threadIdx.x >> 5;
    const float* src = x + (size_t)cih * 32;
#pragma unroll
    for (int i = 0; i < 4; ++i) {
        int b = grp + 8 * i;
        tile[b][lane] = src[(size_t)b * 65536 + lane];
    }
    __syncthreads();
    float* dst = g_xt + (size_t)cih * 1024;
#pragma unroll
    for (int i = 0; i < 4; ++i) {
        int w = grp + 8 * i;
        dst[w * 32 + lane] = tile[lane][w];
    }
}

__device__ __forceinline__ uint32_t f2tf32(float v) {
    uint32_t r;
    asm("cvt.rna.tf32.f32 %0, %1;" : "=r"(r) : "f"(v));
    return r;
}

#define MMA(d, a, b) \
    asm volatile("mma.sync.aligned.m16n8k8.row.col.f32.tf32.tf32.f32 " \
        "{%0,%1,%2,%3}, {%4,%5,%6,%7}, {%8,%9}, {%0,%1,%2,%3};" \
        : "+f"(d[0]), "+f"(d[1]), "+f"(d[2]), "+f"(d[3]) \
        : "r"(a[0]), "r"(a[1]), "r"(a[2]), "r"(a[3]), "r"(b[0]), "r"(b[1]))

// smem: fragment-packed operand tiles (KT=32 k per tile)
//   A (= X, M=32 b): A_hi/A_lo: [reg(4)][m(2)*4 + k8(4)][lane(32)] = 1024 floats each
//   B (= W, N=64 co): B_hi/B_lo: [reg(2)][n8(8)*4 + k8(4)][lane(32)] = 2048 floats each
// layout = sAB: A_hi[0..1024) A_lo[1024..2048) B_hi[2048..4096) B_lo[4096..6144)
__global__ __launch_bounds__(128)
void local2d_mma(const float* __restrict__ wgt,   // [pos][co][k]
                 const float* __restrict__ bias,  // [co][pos]
                 float* __restrict__ out)         // [b][co][pos]
{
    __shared__ float sAB[6144];
    __shared__ int xoffs[KTOT];

    int pos = blockIdx.x, y = pos >> 5, x = pos & 31;
    int tid = threadIdx.x, w = tid >> 5, lane = tid & 31;

    float* A_hi = sAB;
    float* A_lo = sAB + 1024;
    float* B_hi = sAB + 2048;
    float* B_lo = sAB + 4096;

    for (int k = tid; k < KTOT; k += 128) {
        int ci = k / 9, rr = k - ci * 9, ki = rr / 3, kj = rr - ki * 3;
        int iy = y + ki - 1, ix = x + kj - 1;
        xoffs[k] = ((unsigned)iy < 32u && (unsigned)ix < 32u)
                     ? ((ci * 32 + iy) * 32 + ix) * 32 : -1;
    }
    __syncthreads();

    const float* wbase = wgt + (size_t)pos * (COUT * KTOT);

    // K split across warps: warp w owns k8 = w in every tile.
    float acc[2][8][4];
#pragma unroll
    for (int m = 0; m < 2; ++m)
#pragma unroll
        for (int n = 0; n < 8; ++n)
#pragma unroll
            for (int c = 0; c < 4; ++c) acc[m][n][c] = 0.f;

    // X staging constants for this thread
    int sb   = lane;               // batch this thread loads
    int rb   = (sb >> 3) & 1;      // A reg low bit (row>=8)
    int sm_  = sb >> 4;            // A m-tile
    int loff = 4 * (sb & 7);       // lane group offset in frag

    for (int t = 0; t < NTILES; ++t) {
        // ---- stage W -> B frags (coalesced LDG.128, conflict-free STS.128) ----
#pragma unroll
        for (int i = 0; i < 4; ++i) {
            int idx = tid + i * 128;           // 0..511
            int co = idx >> 3, kq4 = idx & 7;  // k0 = kq4*4
            float4 v = *(const float4*)(wbase + co * KTOT + t * KT + kq4 * 4);
            uint32_t h0 = f2tf32(v.x), h1 = f2tf32(v.y), h2 = f2tf32(v.z), h3 = f2tf32(v.w);
            uint32_t l0 = f2tf32(v.x - __uint_as_float(h0));
            uint32_t l1 = f2tf32(v.y - __uint_as_float(h1));
            uint32_t l2 = f2tf32(v.z - __uint_as_float(h2));
            uint32_t l3 = f2tf32(v.w - __uint_as_float(h3));
            int reg = kq4 & 1, k8 = kq4 >> 1;
            int dst = ((reg * 32 + (co >> 3) * 4 + k8) * 32 + 4 * (co & 7));
            *(uint4*)(B_hi + dst) = make_uint4(h0, h1, h2, h3);
            *(uint4*)(B_lo + dst) = make_uint4(l0, l1, l2, l3);
        }
        // ---- stage X -> A frags (coalesced LDG.32 over b, STS.128) ----
        {
            uint32_t h[8], l[8];
#pragma unroll
            for (int i = 0; i < 8; ++i) {
                int off = xoffs[t * KT + w * 8 + i];
                float v = (off >= 0) ? g_xt[off + sb] : 0.f;
                h[i] = f2tf32(v);
                l[i] = f2tf32(v - __uint_as_float(h[i]));
            }
            int d0 = ((rb * 8 + sm_ * 4 + w) * 32 + loff);
            int d2 = (((rb + 2) * 8 + sm_ * 4 + w) * 32 + loff);
            *(uint4*)(A_hi + d0) = make_uint4(h[0], h[1], h[2], h[3]);
            *(uint4*)(A_hi + d2) = make_uint4(h[4], h[5], h[6], h[7]);
            *(uint4*)(A_lo + d0) = make_uint4(l[0], l[1], l[2], l[3]);
            *(uint4*)(A_lo + d2) = make_uint4(l[4], l[5], l[6], l[7]);
        }
        __syncthreads();

        // ---- compute: warp w consumes k8 = w ----
        uint32_t ah[2][4], al[2][4];
#pragma unroll
        for (int m = 0; m < 2; ++m)
#pragma unroll
            for (int r = 0; r < 4; ++r) {
                ah[m][r] = __float_as_uint(A_hi[(r * 8 + m * 4 + w) * 32 + lane]);
                al[m][r] = __float_as_uint(A_lo[(r * 8 + m * 4 + w) * 32 + lane]);
            }
#pragma unroll
        for (int n = 0; n < 8; ++n) {
            uint32_t bh[2], bl[2];
#pragma unroll
            for (int r = 0; r < 2; ++r) {
                bh[r] = __float_as_uint(B_hi[(r * 32 + n * 4 + w) * 32 + lane]);
                bl[r] = __float_as_uint(B_lo[(r * 32 + n * 4 + w) * 32 + lane]);
            }
#pragma unroll
            for (int m = 0; m < 2; ++m) {
                MMA(acc[m][n], ah[m], bh);   // hi*hi
                MMA(acc[m][n], ah[m], bl);   // hi*lo
                MMA(acc[m][n], al[m], bh);   // lo*hi
            }
        }
        __syncthreads();
    }

    // ---- cross-warp K reduction through smem (warps 1-3 park partials) ----
    if (w >= 1) {
        float* buf = sAB + (w - 1) * 2048;
#pragma unroll
        for (int m = 0; m < 2; ++m)
#pragma unroll
            for (int n = 0; n < 8; ++n)
                *(float4*)(buf + ((m * 8 + n) * 32 + lane) * 4) =
                    make_float4(acc[m][n][0], acc[m][n][1], acc[m][n][2], acc[m][n][3]);
    }
    __syncthreads();
    if (w == 0) {
#pragma unroll
        for (int m = 0; m < 2; ++m)
#pragma unroll
            for (int n = 0; n < 8; ++n) {
#pragma unroll
                for (int ww = 0; ww < 3; ++ww) {
                    float4 p = *(float4*)(sAB + ww * 2048 + ((m * 8 + n) * 32 + lane) * 4);
                    acc[m][n][0] += p.x; acc[m][n][1] += p.y;
                    acc[m][n][2] += p.z; acc[m][n][3] += p.w;
                }
                int co0 = n * 8 + 2 * (lane & 3);
                int b0  = m * 16 + (lane >> 2);
                float bv0 = bias[(size_t)co0 * 1024 + pos];
                float bv1 = bias[(size_t)(co0 + 1) * 1024 + pos];
                out[((size_t)b0 * 64 + co0) * 1024 + pos]           = acc[m][n][0] + bv0;
                out[((size_t)b0 * 64 + co0 + 1) * 1024 + pos]       = acc[m][n][1] + bv1;
                out[((size_t)(b0 + 8) * 64 + co0) * 1024 + pos]     = acc[m][n][2] + bv0;
                out[((size_t)(b0 + 8) * 64 + co0 + 1) * 1024 + pos] = acc[m][n][3] + bv1;
            }
    }
}

extern "C" void kernel_launch(void* const* d_in, const int* in_sizes, int n_in,
                              void* d_out, int out_size) {
    const float* x    = (const float*)d_in[0];
    const float* wgt  = (const float*)d_in[1];
    const float* bias = (const float*)d_in[2];
    float* out = (float*)d_out;

    transpose_x_kernel<<<CIN * HW, 256>>>(x);
    local2d_mma<<<HW * HW, 128>>>(wgt, bias, out);
}

// round 7
// speedup vs baseline: 3.1892x; 2.5302x over previous
#include <cuda_runtime.h>
#include <cstdint>

#define CIN 64
#define COUT 64
#define HW 32
#define KTOT 576
#define KT 32
#define NTILES 18
#define WS_ROW 36   // 32 k + 4 pad (144B, 16B-aligned)
#define XS_ROW 36   // 32 b + 4 pad
#define WS_WORDS (64 * WS_ROW)   // 2304
#define XS_WORDS (32 * XS_ROW)   // 1152
#define STAGE_WORDS (WS_WORDS + XS_WORDS)  // 3456 floats = 13824B

// x transposed to [ci][h][w][b] (batch innermost -> contiguous 128B rows)
__device__ float g_xt[CIN * HW * HW * 32];

__global__ void transpose_x_kernel(const float* __restrict__ x) {
    __shared__ float tile[32][33];
    int cih = blockIdx.x;
    int lane = threadIdx.x & 31;
    int grp  = threadIdx.x >> 5;
    const float* src = x + (size_t)cih * 32;
#pragma unroll
    for (int i = 0; i < 4; ++i) {
        int b = grp + 8 * i;
        tile[b][lane] = src[(size_t)b * 65536 + lane];
    }
    __syncthreads();
    float* dst = g_xt + (size_t)cih * 1024;
#pragma unroll
    for (int i = 0; i < 4; ++i) {
        int w = grp + 8 * i;
        dst[w * 32 + lane] = tile[lane][w];
    }
}

__device__ __forceinline__ uint32_t smem_u32(const void* p) {
    uint32_t a;
    asm("{ .reg .u64 t; cvta.to.shared.u64 t, %1; cvt.u32.u64 %0, t; }" : "=r"(a) : "l"(p));
    return a;
}

// hi = top-16 truncation of pair (f0=low element), lo = bf16(f - hi) pair
__device__ __forceinline__ void split_pair(float f0, float f1, uint32_t& hi2, uint32_t& lo2) {
    asm("prmt.b32 %0, %1, %2, 0x7632;" : "=r"(hi2) : "r"(__float_as_uint(f0)), "r"(__float_as_uint(f1)));
    float h0 = __uint_as_float(__float_as_uint(f0) & 0xFFFF0000u);
    float h1 = __uint_as_float(__float_as_uint(f1) & 0xFFFF0000u);
    asm("cvt.rn.bf16x2.f32 %0, %1, %2;" : "=r"(lo2) : "f"(f1 - h1), "f"(f0 - h0));
}

#define MMA16(d, a, b) \
    asm volatile("mma.sync.aligned.m16n8k16.row.col.f32.bf16.bf16.f32 " \
        "{%0,%1,%2,%3}, {%4,%5,%6,%7}, {%8,%9}, {%0,%1,%2,%3};" \
        : "+f"(d[0]), "+f"(d[1]), "+f"(d[2]), "+f"(d[3]) \
        : "r"(a[0]), "r"(a[1]), "r"(a[2]), "r"(a[3]), "r"(b[0]), "r"(b[1]))

#define CPA16(dst, src, sz) \
    asm volatile("cp.async.cg.shared.global [%0], [%1], 16, %2;" \
        :: "r"(dst), "l"(src), "r"(sz) : "memory")
#define CPA_COMMIT() asm volatile("cp.async.commit_group;" ::: "memory")
#define CPA_WAIT1()  asm volatile("cp.async.wait_group 1;" ::: "memory")

__global__ __launch_bounds__(256, 4)
void local2d_mma(const float* __restrict__ wgt,   // [pos][co][k]
                 const float* __restrict__ bias,  // [co][pos]
                 float* __restrict__ out)         // [b][co][pos]
{
    __shared__ __align__(16) float stg[2][STAGE_WORDS];  // [ws | xs] per stage
    __shared__ int xoffs[KTOT];
    __shared__ float sbias[64];

    int pos = blockIdx.x, y = pos >> 5, x = pos & 31;
    int tid = threadIdx.x, w = tid >> 5, lane = tid & 31;
    int g = lane >> 2, tq = lane & 3;
    int kw = w & 1;        // k16-chunk within tile (0..1)
    int nh = w >> 1;       // n-tile group (0..3), owns ntiles {2nh, 2nh+1}

    for (int k = tid; k < KTOT; k += 256) {
        int ci = k / 9, rr = k - ci * 9, ki = rr / 3, kj = rr - ki * 3;
        int iy = y + ki - 1, ix = x + kj - 1;
        xoffs[k] = ((unsigned)iy < 32u && (unsigned)ix < 32u)
                     ? ((ci * 32 + iy) * 32 + ix) * 32 : -1;
    }
    if (tid < 64) sbias[tid] = bias[(size_t)tid * 1024 + pos];
    __syncthreads();

    const float* wbase = wgt + (size_t)pos * (COUT * KTOT);
    uint32_t stg_a = smem_u32(stg);

    // staging indices (fixed per thread)
    int wco0 = tid >> 3, wch = tid & 7;            // W chunk 0: co = wco0
    int wco1 = (tid + 256) >> 3;                   // W chunk 1: co = wco1
    int xk = tid >> 3, xch = tid & 7;              // X chunk: k row

    auto issue = [&](int t, int s) {
        uint32_t ws_b = stg_a + (uint32_t)s * (STAGE_WORDS * 4);
        uint32_t xs_b = ws_b + WS_WORDS * 4;
        const float* wsrc0 = wbase + wco0 * KTOT + t * KT + wch * 4;
        const float* wsrc1 = wbase + wco1 * KTOT + t * KT + wch * 4;
        CPA16(ws_b + (uint32_t)(wco0 * WS_ROW + wch * 4) * 4, wsrc0, 16);
        CPA16(ws_b + (uint32_t)(wco1 * WS_ROW + wch * 4) * 4, wsrc1, 16);
        int off = xoffs[t * KT + xk];
        const float* xsrc = g_xt + (off >= 0 ? off : 0) + xch * 4;
        CPA16(xs_b + (uint32_t)(xk * XS_ROW + xch * 4) * 4, xsrc, off >= 0 ? 16 : 0);
    };

    float acc[2][2][4];
#pragma unroll
    for (int mt = 0; mt < 2; ++mt)
#pragma unroll
        for (int n = 0; n < 2; ++n)
#pragma unroll
            for (int c = 0; c < 4; ++c) acc[mt][n][c] = 0.f;

    issue(0, 0); CPA_COMMIT();
    issue(1, 1); CPA_COMMIT();

    for (int t = 0; t < NTILES; ++t) {
        int s = t & 1;
        CPA_WAIT1();
        __syncthreads();

        const float* ws = stg[s];
        const float* xs = stg[s] + WS_WORDS;
        int kb = kw * 16 + 2 * tq;   // k base for this warp's frag

        // ---- A frags: convert raw f32 -> bf16 hi/lo (conflict-free LDS.32) ----
        uint32_t ah[2][4], al[2][4];
#pragma unroll
        for (int mt = 0; mt < 2; ++mt) {
#pragma unroll
            for (int ko = 0; ko < 2; ++ko)       // k +0 / +8
#pragma unroll
                for (int ro = 0; ro < 2; ++ro) { // row +0 / +8
                    int m = mt * 16 + ro * 8 + g;
                    float f0 = xs[(kb + 8 * ko) * XS_ROW + m];
                    float f1 = xs[(kb + 8 * ko + 1) * XS_ROW + m];
                    int r = ko * 2 + ro;         // a0..a3 = (ro,ko): (0,0),(1,0),(0,1),(1,1)
                    split_pair(f0, f1, ah[mt][r], al[mt][r]);
                }
        }

        // ---- per n-tile: B frags + 3 MMAs x 2 m-tiles ----
#pragma unroll
        for (int n = 0; n < 2; ++n) {
            int co = (nh * 2 + n) * 8 + g;
            uint32_t bh[2], bl[2];
#pragma unroll
            for (int ko = 0; ko < 2; ++ko) {
                float2 f = *(const float2*)&ws[co * WS_ROW + kb + 8 * ko];
                split_pair(f.x, f.y, bh[ko], bl[ko]);
            }
#pragma unroll
            for (int mt = 0; mt < 2; ++mt) {
                MMA16(acc[mt][n], ah[mt], bh);   // hi*hi
                MMA16(acc[mt][n], ah[mt], bl);   // hi*lo
                MMA16(acc[mt][n], al[mt], bh);   // lo*hi
            }
        }
        __syncthreads();
        if (t + 2 < NTILES) issue(t + 2, s);
        CPA_COMMIT();
    }

    // ---- reduce across kw pairs via smem, then store ----
    __syncthreads();
    float* red = stg[0];
    if (kw == 1) {
        float* base = red + nh * 512;
#pragma unroll
        for (int mt = 0; mt < 2; ++mt)
#pragma unroll
            for (int n = 0; n < 2; ++n)
#pragma unroll
                for (int c = 0; c < 4; ++c)
                    base[((mt * 2 + n) * 4 + c) * 32 + lane] = acc[mt][n][c];
    }
    __syncthreads();
    if (kw == 0) {
        const float* base = red + nh * 512;
#pragma unroll
        for (int mt = 0; mt < 2; ++mt)
#pragma unroll
            for (int n = 0; n < 2; ++n) {
                int co0 = (nh * 2 + n) * 8 + 2 * tq;
#pragma unroll
                for (int c = 0; c < 4; ++c) {
                    float v = acc[mt][n][c] + base[((mt * 2 + n) * 4 + c) * 32 + lane];
                    int b  = mt * 16 + g + 8 * (c >> 1);
                    int co = co0 + (c & 1);
                    out[((size_t)b * 64 + co) * 1024 + pos] = v + sbias[co];
                }
            }
    }
}

extern "C" void kernel_launch(void* const* d_in, const int* in_sizes, int n_in,
                              void* d_out, int out_size) {
    const float* x    = (const float*)d_in[0];
    const float* wgt  = (const float*)d_in[1];
    const float* bias = (const float*)d_in[2];
    float* out = (float*)d_out;

    transpose_x_kernel<<<CIN * HW, 256>>>(x);
    local2d_mma<<<HW * HW, 256>>>(wgt, bias, out);
}

// round 8
// speedup vs baseline: 3.2098x; 1.0065x over previous
#include <cuda_runtime.h>
#include <cuda_bf16.h>
#include <cstdint>

#define CIN 64
#define COUT 64
#define HW 32
#define KTOT 576
#define KT 32
#define NTILES 18
#define WS_ROW 36            // f32 words per W row (144B)
#define WS_BYTES (64 * WS_ROW * 4)       // 9216
#define XR 40                // bf16 per X row (80B, ldmatrix conflict-free)
#define XH_BYTES (32 * XR * 2)           // 2560
#define STAGE_BYTES (WS_BYTES + 2 * XH_BYTES)  // 14336

// x as bf16 hi/lo, layout [ci][h][w][b] (b innermost, 64B rows)
__device__ __nv_bfloat16 g_xh[CIN * HW * HW * 32];
__device__ __nv_bfloat16 g_xl[CIN * HW * HW * 32];

__global__ void transpose_x_kernel(const float* __restrict__ x) {
    __shared__ float tile[32][33];
    int cih = blockIdx.x;
    int lane = threadIdx.x & 31;
    int grp  = threadIdx.x >> 5;
    const float* src = x + (size_t)cih * 32;
#pragma unroll
    for (int i = 0; i < 4; ++i) {
        int b = grp + 8 * i;
        tile[b][lane] = src[(size_t)b * 65536 + lane];
    }
    __syncthreads();
    size_t base = (size_t)cih * 1024;
#pragma unroll
    for (int i = 0; i < 4; ++i) {
        int w = grp + 8 * i;
        float v = tile[lane][w];
        __nv_bfloat16 h = __float2bfloat16(v);
        __nv_bfloat16 l = __float2bfloat16(v - __bfloat162float(h));
        g_xh[base + w * 32 + lane] = h;
        g_xl[base + w * 32 + lane] = l;
    }
}

__device__ __forceinline__ uint32_t smem_u32(const void* p) {
    uint32_t a;
    asm("{ .reg .u64 t; cvta.to.shared.u64 t, %1; cvt.u32.u64 %0, t; }" : "=r"(a) : "l"(p));
    return a;
}

// hi = top-16 truncation of pair (f0=low element), lo = bf16(f - hi) pair
__device__ __forceinline__ void split_pair(float f0, float f1, uint32_t& hi2, uint32_t& lo2) {
    asm("prmt.b32 %0, %1, %2, 0x7632;" : "=r"(hi2) : "r"(__float_as_uint(f0)), "r"(__float_as_uint(f1)));
    float h0 = __uint_as_float(__float_as_uint(f0) & 0xFFFF0000u);
    float h1 = __uint_as_float(__float_as_uint(f1) & 0xFFFF0000u);
    asm("cvt.rn.bf16x2.f32 %0, %1, %2;" : "=r"(lo2) : "f"(f1 - h1), "f"(f0 - h0));
}

#define MMA16(d, a, b) \
    asm volatile("mma.sync.aligned.m16n8k16.row.col.f32.bf16.bf16.f32 " \
        "{%0,%1,%2,%3}, {%4,%5,%6,%7}, {%8,%9}, {%0,%1,%2,%3};" \
        : "+f"(d[0]), "+f"(d[1]), "+f"(d[2]), "+f"(d[3]) \
        : "r"(a[0]), "r"(a[1]), "r"(a[2]), "r"(a[3]), "r"(b[0]), "r"(b[1]))

#define LDSMT4(r, a) \
    asm volatile("ldmatrix.sync.aligned.m8n8.x4.trans.shared.b16 {%0,%1,%2,%3}, [%4];" \
        : "=r"(r[0]), "=r"(r[1]), "=r"(r[2]), "=r"(r[3]) : "r"(a))

#define CPA16(dst, src, sz) \
    asm volatile("cp.async.cg.shared.global [%0], [%1], 16, %2;" \
        :: "r"(dst), "l"(src), "r"(sz) : "memory")
#define CPA_COMMIT() asm volatile("cp.async.commit_group;" ::: "memory")
#define CPA_WAIT1()  asm volatile("cp.async.wait_group 1;" ::: "memory")

__global__ __launch_bounds__(256, 4)
void local2d_mma(const float* __restrict__ wgt,   // [pos][co][k]
                 const float* __restrict__ bias,  // [co][pos]
                 float* __restrict__ out)         // [b][co][pos]
{
    __shared__ __align__(16) uint8_t stg[2][STAGE_BYTES];  // [W f32 | Xhi b16 | Xlo b16]
    __shared__ int xoffs[KTOT];
    __shared__ float sbias[64];

    int pos = blockIdx.x, y = pos >> 5, x = pos & 31;
    int tid = threadIdx.x, w = tid >> 5, lane = tid & 31;
    int g = lane >> 2, tq = lane & 3;
    int kw = w & 1;        // k16-chunk within 32-k tile
    int nh = w >> 1;       // n-tile group (0..3)

    for (int k = tid; k < KTOT; k += 256) {
        int ci = k / 9, rr = k - ci * 9, ki = rr / 3, kj = rr - ki * 3;
        int iy = y + ki - 1, ix = x + kj - 1;
        xoffs[k] = ((unsigned)iy < 32u && (unsigned)ix < 32u)
                     ? ((ci * 32 + iy) * 32 + ix) * 32 : -1;
    }
    if (tid < 64) sbias[tid] = bias[(size_t)tid * 1024 + pos];
    __syncthreads();

    const float* wbase = wgt + (size_t)pos * (COUT * KTOT);
    uint32_t stg_a = smem_u32(stg);

    // staging indices
    int wco0 = tid >> 3, wch = tid & 7;           // W: 2 chunks/thread
    int wco1 = (tid + 256) >> 3;
    int xarr = tid >> 7;                          // 0=hi, 1=lo
    int xk   = (tid >> 2) & 31;                   // k row
    int xch  = tid & 3;                           // 16B chunk in 64B row

    const __nv_bfloat16* xsrc_base = xarr ? g_xl : g_xh;

    auto issue = [&](int t, int s) {
        uint32_t ws_b = stg_a + (uint32_t)s * STAGE_BYTES;
        CPA16(ws_b + (uint32_t)(wco0 * WS_ROW + wch * 4) * 4,
              wbase + wco0 * KTOT + t * KT + wch * 4, 16);
        CPA16(ws_b + (uint32_t)(wco1 * WS_ROW + wch * 4) * 4,
              wbase + wco1 * KTOT + t * KT + wch * 4, 16);
        int off = xoffs[t * KT + xk];
        const __nv_bfloat16* xsrc = xsrc_base + (off >= 0 ? off : 0) + xch * 8;
        uint32_t xdst = ws_b + WS_BYTES + (uint32_t)xarr * XH_BYTES
                        + (uint32_t)(xk * XR + xch * 8) * 2;
        CPA16(xdst, xsrc, off >= 0 ? 16 : 0);
    };

    float acc[2][2][4];
#pragma unroll
    for (int mt = 0; mt < 2; ++mt)
#pragma unroll
        for (int n = 0; n < 2; ++n)
#pragma unroll
            for (int c = 0; c < 4; ++c) acc[mt][n][c] = 0.f;

    issue(0, 0); CPA_COMMIT();
    issue(1, 1); CPA_COMMIT();

    // ldmatrix per-lane address pieces: row = kb + ((lane&16)>>1) + (lane&7), col = mt*16 + (lane&8)
    int lrow = (kw * 16) + ((lane & 16) >> 1) + (lane & 7);
    int lcol = (lane & 8);

    for (int t = 0; t < NTILES; ++t) {
        int s = t & 1;
        CPA_WAIT1();
        __syncthreads();

        uint32_t xh_b = stg_a + (uint32_t)s * STAGE_BYTES + WS_BYTES;
        const float* ws = (const float*)stg[s];

        // ---- A frags: ldmatrix.trans from bf16 hi/lo tiles ----
        uint32_t ah[2][4], al[2][4];
#pragma unroll
        for (int mt = 0; mt < 2; ++mt) {
            uint32_t a_addr = xh_b + (uint32_t)(lrow * XR + mt * 16 + lcol) * 2;
            LDSMT4(ah[mt], a_addr);
            LDSMT4(al[mt], a_addr + XH_BYTES);
        }

        // ---- per n-tile: B frags (convert-at-consume) + 3 MMAs x 2 m-tiles ----
        int kb = kw * 16 + 2 * tq;
#pragma unroll
        for (int n = 0; n < 2; ++n) {
            int co = (nh * 2 + n) * 8 + g;
            uint32_t bh[2], bl[2];
#pragma unroll
            for (int ko = 0; ko < 2; ++ko) {
                float2 f = *(const float2*)&ws[co * WS_ROW + kb + 8 * ko];
                split_pair(f.x, f.y, bh[ko], bl[ko]);
            }
#pragma unroll
            for (int mt = 0; mt < 2; ++mt) {
                MMA16(acc[mt][n], ah[mt], bh);   // hi*hi
                MMA16(acc[mt][n], ah[mt], bl);   // hi*lo
                MMA16(acc[mt][n], al[mt], bh);   // lo*hi
            }
        }
        __syncthreads();
        if (t + 2 < NTILES) issue(t + 2, s);
        CPA_COMMIT();
    }

    // ---- reduce across kw pairs via smem, then store ----
    __syncthreads();
    float* red = (float*)stg[0];
    if (kw == 1) {
        float* base = red + nh * 512;
#pragma unroll
        for (int mt = 0; mt < 2; ++mt)
#pragma unroll
            for (int n = 0; n < 2; ++n)
#pragma unroll
                for (int c = 0; c < 4; ++c)
                    base[((mt * 2 + n) * 4 + c) * 32 + lane] = acc[mt][n][c];
    }
    __syncthreads();
    if (kw == 0) {
        const float* base = red + nh * 512;
#pragma unroll
        for (int mt = 0; mt < 2; ++mt)
#pragma unroll
            for (int n = 0; n < 2; ++n) {
                int co0 = (nh * 2 + n) * 8 + 2 * tq;
#pragma unroll
                for (int c = 0; c < 4; ++c) {
                    float v = acc[mt][n][c] + base[((mt * 2 + n) * 4 + c) * 32 + lane];
                    int b  = mt * 16 + g + 8 * (c >> 1);
                    int co = co0 + (c & 1);
                    out[((size_t)b * 64 + co) * 1024 + pos] = v + sbias[co];
                }
            }
    }
}

extern "C" void kernel_launch(void* const* d_in, const int* in_sizes, int n_in,
                              void* d_out, int out_size) {
    const float* x    = (const float*)d_in[0];
    const float* wgt  = (const float*)d_in[1];
    const float* bias = (const float*)d_in[2];
    float* out = (float*)d_out;

    transpose_x_kernel<<<CIN * HW, 256>>>(x);
    local2d_mma<<<HW * HW, 256>>>(wgt, bias, out);
}

// round 9
// speedup vs baseline: 3.4078x; 1.0617x over previous
#include <cuda_runtime.h>
#include <cuda_bf16.h>
#include <cuda.h>
#include <cstdint>

#define CIN 64
#define COUT 64
#define HW 32
#define KTOT 576
#define KT 32
#define NTILES 18
#define WS_BYTES 8192                     // 64 rows x 128B (TMA SW128 box)
#define XR 40                             // bf16 per X row (80B, ldmatrix conflict-free)
#define XH_BYTES (32 * XR * 2)            // 2560
#define STAGE_BYTES (WS_BYTES + 2 * XH_BYTES)  // 13312 (13*1024)

// x as bf16 hi/lo, layout [ci][h][w][b] (b innermost, 64B rows)
__device__ __nv_bfloat16 g_xh[CIN * HW * HW * 32];
__device__ __nv_bfloat16 g_xl[CIN * HW * HW * 32];

__global__ void transpose_x_kernel(const float* __restrict__ x) {
    __shared__ float tile[32][33];
    int cih = blockIdx.x;
    int lane = threadIdx.x & 31;
    int grp  = threadIdx.x >> 5;
    const float* src = x + (size_t)cih * 32;
#pragma unroll
    for (int i = 0; i < 4; ++i) {
        int b = grp + 8 * i;
        tile[b][lane] = src[(size_t)b * 65536 + lane];
    }
    __syncthreads();
    size_t base = (size_t)cih * 1024;
#pragma unroll
    for (int i = 0; i < 4; ++i) {
        int w = grp + 8 * i;
        float v = tile[lane][w];
        __nv_bfloat16 h = __float2bfloat16(v);
        __nv_bfloat16 l = __float2bfloat16(v - __bfloat162float(h));
        g_xh[base + w * 32 + lane] = h;
        g_xl[base + w * 32 + lane] = l;
    }
}

__device__ __forceinline__ uint32_t smem_u32(const void* p) {
    uint32_t a;
    asm("{ .reg .u64 t; cvta.to.shared.u64 t, %1; cvt.u32.u64 %0, t; }" : "=r"(a) : "l"(p));
    return a;
}

// hi = top-16 truncation of pair (f0=low element), lo = bf16(f - hi) pair
__device__ __forceinline__ void split_pair(float f0, float f1, uint32_t& hi2, uint32_t& lo2) {
    asm("prmt.b32 %0, %1, %2, 0x7632;" : "=r"(hi2) : "r"(__float_as_uint(f0)), "r"(__float_as_uint(f1)));
    float h0 = __uint_as_float(__float_as_uint(f0) & 0xFFFF0000u);
    float h1 = __uint_as_float(__float_as_uint(f1) & 0xFFFF0000u);
    asm("cvt.rn.bf16x2.f32 %0, %1, %2;" : "=r"(lo2) : "f"(f1 - h1), "f"(f0 - h0));
}

#define MMA16(d, a, b) \
    asm volatile("mma.sync.aligned.m16n8k16.row.col.f32.bf16.bf16.f32 " \
        "{%0,%1,%2,%3}, {%4,%5,%6,%7}, {%8,%9}, {%0,%1,%2,%3};" \
        : "+f"(d[0]), "+f"(d[1]), "+f"(d[2]), "+f"(d[3]) \
        : "r"(a[0]), "r"(a[1]), "r"(a[2]), "r"(a[3]), "r"(b[0]), "r"(b[1]))

#define LDSMT4(r, a) \
    asm volatile("ldmatrix.sync.aligned.m8n8.x4.trans.shared.b16 {%0,%1,%2,%3}, [%4];" \
        : "=r"(r[0]), "=r"(r[1]), "=r"(r[2]), "=r"(r[3]) : "r"(a))

#define CPA16(dst, src, sz) \
    asm volatile("cp.async.cg.shared.global [%0], [%1], 16, %2;" \
        :: "r"(dst), "l"(src), "r"(sz) : "memory")
#define CPA_COMMIT() asm volatile("cp.async.commit_group;" ::: "memory")
#define CPA_WAIT1()  asm volatile("cp.async.wait_group 1;" ::: "memory")

__global__ __launch_bounds__(256, 4)
void local2d_mma(const __grid_constant__ CUtensorMap tmap,
                 const float* __restrict__ bias,  // [co][pos]
                 float* __restrict__ out)         // [b][co][pos]
{
    __shared__ __align__(1024) uint8_t stg[2][STAGE_BYTES];  // [W(TMA,SW128) | Xhi | Xlo]
    __shared__ uint64_t mbar[2];
    __shared__ int xoffs[KTOT];
    __shared__ float sbias[64];

    int pos = blockIdx.x, y = pos >> 5, x = pos & 31;
    int tid = threadIdx.x, w = tid >> 5, lane = tid & 31;
    int g = lane >> 2, tq = lane & 3;
    int kw = w & 1;        // k16-chunk within 32-k tile
    int nh = w >> 1;       // n-tile group (0..3)

    for (int k = tid; k < KTOT; k += 256) {
        int ci = k / 9, rr = k - ci * 9, ki = rr / 3, kj = rr - ki * 3;
        int iy = y + ki - 1, ix = x + kj - 1;
        xoffs[k] = ((unsigned)iy < 32u && (unsigned)ix < 32u)
                     ? ((ci * 32 + iy) * 32 + ix) * 32 : -1;
    }
    if (tid < 64) sbias[tid] = bias[(size_t)tid * 1024 + pos];
    uint32_t mb0 = smem_u32(&mbar[0]);
    if (tid == 0) {
        asm volatile("mbarrier.init.shared.b64 [%0], %1;" :: "r"(mb0), "r"(1) : "memory");
        asm volatile("mbarrier.init.shared.b64 [%0], %1;" :: "r"(mb0 + 8), "r"(1) : "memory");
    }
    __syncthreads();

    uint32_t stg_a = smem_u32(stg);

    // X staging indices
    int xarr = tid >> 7;                          // 0=hi, 1=lo
    int xk   = (tid >> 2) & 31;                   // k row
    int xch  = tid & 3;                           // 16B chunk in 64B row
    const __nv_bfloat16* xsrc_base = xarr ? g_xl : g_xh;

    auto issue = [&](int t, int s) {
        uint32_t ws_b = stg_a + (uint32_t)s * STAGE_BYTES;
        if (tid == 0) {
            uint32_t mb = mb0 + 8 * s;
            asm volatile("mbarrier.arrive.expect_tx.shared.b64 _, [%0], %1;"
                         :: "r"(mb), "r"(WS_BYTES) : "memory");
            asm volatile(
                "cp.async.bulk.tensor.2d.shared::cta.global.tile.mbarrier::complete_tx::bytes "
                "[%0], [%1, {%2, %3}], [%4];"
                :: "r"(ws_b), "l"(&tmap), "r"(t * KT), "r"(pos * 64), "r"(mb) : "memory");
        }
        int off = xoffs[t * KT + xk];
        const __nv_bfloat16* xsrc = xsrc_base + (off >= 0 ? off : 0) + xch * 8;
        uint32_t xdst = ws_b + WS_BYTES + (uint32_t)xarr * XH_BYTES
                        + (uint32_t)(xk * XR + xch * 8) * 2;
        CPA16(xdst, xsrc, off >= 0 ? 16 : 0);
    };

    float acc[2][2][4];
#pragma unroll
    for (int mt = 0; mt < 2; ++mt)
#pragma unroll
        for (int n = 0; n < 2; ++n)
#pragma unroll
            for (int c = 0; c < 4; ++c) acc[mt][n][c] = 0.f;

    issue(0, 0); CPA_COMMIT();
    issue(1, 1); CPA_COMMIT();

    // ldmatrix per-lane address: row = kw*16 + ((lane&16)>>1) + (lane&7), col base = lane&8
    int lrow = (kw * 16) + ((lane & 16) >> 1) + (lane & 7);
    int lcol = (lane & 8);

    for (int t = 0; t < NTILES; ++t) {
        int s = t & 1;
        // wait W (TMA mbarrier, parity flips every 2 tiles per stage)
        {
            uint32_t mb = mb0 + 8 * s;
            uint32_t ph = (t >> 1) & 1;
            asm volatile(
                "{ .reg .pred P;\n\t"
                "WL%=: mbarrier.try_wait.parity.acquire.cta.shared::cta.b64 P, [%0], %1, 0x989680;\n\t"
                "@P bra WD%=;\n\t"
                "bra WL%=;\n\t"
                "WD%=: }"
                :: "r"(mb), "r"(ph) : "memory");
        }
        CPA_WAIT1();           // X for tile t arrived (this thread's groups)
        __syncthreads();       // make all threads' X visible

        uint32_t ws_b = stg_a + (uint32_t)s * STAGE_BYTES;
        uint32_t xh_b = ws_b + WS_BYTES;
        const uint8_t* ws = (const uint8_t*)stg[s];

        // ---- A frags: ldmatrix.trans from bf16 hi/lo tiles ----
        uint32_t ah[2][4], al[2][4];
#pragma unroll
        for (int mt = 0; mt < 2; ++mt) {
            uint32_t a_addr = xh_b + (uint32_t)(lrow * XR + mt * 16 + lcol) * 2;
            LDSMT4(ah[mt], a_addr);
            LDSMT4(al[mt], a_addr + XH_BYTES);
        }

        // ---- per n-tile: B frags (convert-at-consume, SW128 swizzled rows) ----
        int colb = (kw * 16 + 2 * tq) * 4;   // byte offset of k-pair in row
#pragma unroll
        for (int n = 0; n < 2; ++n) {
            int co = (nh * 2 + n) * 8 + g;
            uint32_t bh[2], bl[2];
#pragma unroll
            for (int ko = 0; ko < 2; ++ko) {
                uint32_t byte = (uint32_t)co * 128 + (uint32_t)((colb + ko * 32) ^ ((co & 7) << 4));
                float2 f = *(const float2*)(ws + byte);
                split_pair(f.x, f.y, bh[ko], bl[ko]);
            }
#pragma unroll
            for (int mt = 0; mt < 2; ++mt) {
                MMA16(acc[mt][n], ah[mt], bh);   // hi*hi
                MMA16(acc[mt][n], ah[mt], bl);   // hi*lo
                MMA16(acc[mt][n], al[mt], bh);   // lo*hi
            }
        }
        __syncthreads();
        if (t + 2 < NTILES) issue(t + 2, s);
        CPA_COMMIT();
    }

    // ---- reduce across kw pairs via smem, then store ----
    __syncthreads();
    float* red = (float*)stg[0];
    if (kw == 1) {
        float* base = red + nh * 512;
#pragma unroll
        for (int mt = 0; mt < 2; ++mt)
#pragma unroll
            for (int n = 0; n < 2; ++n)
#pragma unroll
                for (int c = 0; c < 4; ++c)
                    base[((mt * 2 + n) * 4 + c) * 32 + lane] = acc[mt][n][c];
    }
    __syncthreads();
    if (kw == 0) {
        const float* base = red + nh * 512;
#pragma unroll
        for (int mt = 0; mt < 2; ++mt)
#pragma unroll
            for (int n = 0; n < 2; ++n) {
                int co0 = (nh * 2 + n) * 8 + 2 * tq;
#pragma unroll
                for (int c = 0; c < 4; ++c) {
                    float v = acc[mt][n][c] + base[((mt * 2 + n) * 4 + c) * 32 + lane];
                    int b  = mt * 16 + g + 8 * (c >> 1);
                    int co = co0 + (c & 1);
                    out[((size_t)b * 64 + co) * 1024 + pos] = v + sbias[co];
                }
            }
    }
}

typedef CUresult (*EncodeTiledFn)(
    CUtensorMap*, CUtensorMapDataType, cuuint32_t, void*,
    const cuuint64_t*, const cuuint64_t*, const cuuint32_t*, const cuuint32_t*,
    CUtensorMapInterleave, CUtensorMapSwizzle, CUtensorMapL2promotion,
    CUtensorMapFloatOOBfill);

extern "C" void kernel_launch(void* const* d_in, const int* in_sizes, int n_in,
                              void* d_out, int out_size) {
    const float* x    = (const float*)d_in[0];
    const float* wgt  = (const float*)d_in[1];
    const float* bias = (const float*)d_in[2];
    float* out = (float*)d_out;

    // Build W tensormap: 2D (576 k, 65536 pos*co), box (32, 64), SW128.
    void* fn = nullptr;
    cudaDriverEntryPointQueryResult qr;
    cudaGetDriverEntryPoint("cuTensorMapEncodeTiled", &fn, cudaEnableDefault, &qr);
    CUtensorMap tmap;
    cuuint64_t dims[2]    = {576, 65536};
    cuuint64_t strides[1] = {576 * 4};
    cuuint32_t box[2]     = {32, 64};
    cuuint32_t es[2]      = {1, 1};
    ((EncodeTiledFn)fn)(&tmap, CU_TENSOR_MAP_DATA_TYPE_FLOAT32, 2, (void*)wgt,
                        dims, strides, box, es,
                        CU_TENSOR_MAP_INTERLEAVE_NONE, CU_TENSOR_MAP_SWIZZLE_128B,
                        CU_TENSOR_MAP_L2_PROMOTION_L2_128B,
                        CU_TENSOR_MAP_FLOAT_OOB_FILL_NONE);

    transpose_x_kernel<<<CIN * HW, 256>>>(x);
    local2d_mma<<<HW * HW, 256>>>(tmap, bias, out);
}

// round 10
// speedup vs baseline: 3.4234x; 1.0046x over previous
#include <cuda_runtime.h>
#include <cuda_bf16.h>
#include <cuda.h>
#include <cstdint>

#define CIN 64
#define COUT 64
#define HW 32
#define KTOT 576
#define KT 32
#define NTILES 18
#define WS_BYTES 8192                     // 64 rows x 128B (TMA SW128 box)
#define XR 40                             // bf16 per X row (80B, ldmatrix conflict-free)
#define XH_BYTES (32 * XR * 2)            // 2560
#define STAGE_BYTES (WS_BYTES + 2 * XH_BYTES)  // 13312 (13*1024)
#define NSTAGE 3

// x as bf16 hi/lo, layout [ci][h][w][b] (b innermost, 64B rows)
__device__ __nv_bfloat16 g_xh[CIN * HW * HW * 32];
__device__ __nv_bfloat16 g_xl[CIN * HW * HW * 32];

__global__ void transpose_x_kernel(const float* __restrict__ x) {
    __shared__ float tile[32][33];
    int cih = blockIdx.x;
    int lane = threadIdx.x & 31;
    int grp  = threadIdx.x >> 5;
    const float* src = x + (size_t)cih * 32;
#pragma unroll
    for (int i = 0; i < 4; ++i) {
        int b = grp + 8 * i;
        tile[b][lane] = src[(size_t)b * 65536 + lane];
    }
    __syncthreads();
    size_t base = (size_t)cih * 1024;
#pragma unroll
    for (int i = 0; i < 4; ++i) {
        int w = grp + 8 * i;
        float v = tile[lane][w];
        __nv_bfloat16 h = __float2bfloat16(v);
        __nv_bfloat16 l = __float2bfloat16(v - __bfloat162float(h));
        g_xh[base + w * 32 + lane] = h;
        g_xl[base + w * 32 + lane] = l;
    }
}

__device__ __forceinline__ uint32_t smem_u32(const void* p) {
    uint32_t a;
    asm("{ .reg .u64 t; cvta.to.shared.u64 t, %1; cvt.u32.u64 %0, t; }" : "=r"(a) : "l"(p));
    return a;
}

// hi = top-16 truncation of pair (f0=low element), lo = bf16(f - hi) pair
__device__ __forceinline__ void split_pair(float f0, float f1, uint32_t& hi2, uint32_t& lo2) {
    asm("prmt.b32 %0, %1, %2, 0x7632;" : "=r"(hi2) : "r"(__float_as_uint(f0)), "r"(__float_as_uint(f1)));
    float h0 = __uint_as_float(__float_as_uint(f0) & 0xFFFF0000u);
    float h1 = __uint_as_float(__float_as_uint(f1) & 0xFFFF0000u);
    asm("cvt.rn.bf16x2.f32 %0, %1, %2;" : "=r"(lo2) : "f"(f1 - h1), "f"(f0 - h0));
}

#define MMA16(d, a, b) \
    asm volatile("mma.sync.aligned.m16n8k16.row.col.f32.bf16.bf16.f32 " \
        "{%0,%1,%2,%3}, {%4,%5,%6,%7}, {%8,%9}, {%0,%1,%2,%3};" \
        : "+f"(d[0]), "+f"(d[1]), "+f"(d[2]), "+f"(d[3]) \
        : "r"(a[0]), "r"(a[1]), "r"(a[2]), "r"(a[3]), "r"(b[0]), "r"(b[1]))

#define LDSMT4(r, a) \
    asm volatile("ldmatrix.sync.aligned.m8n8.x4.trans.shared.b16 {%0,%1,%2,%3}, [%4];" \
        : "=r"(r[0]), "=r"(r[1]), "=r"(r[2]), "=r"(r[3]) : "r"(a))

#define CPA16(dst, src, sz) \
    asm volatile("cp.async.cg.shared.global [%0], [%1], 16, %2;" \
        :: "r"(dst), "l"(src), "r"(sz) : "memory")
#define CPA_COMMIT() asm volatile("cp.async.commit_group;" ::: "memory")
#define CPA_WAIT1()  asm volatile("cp.async.wait_group 1;" ::: "memory")

__global__ __launch_bounds__(256, 4)
void local2d_mma(const __grid_constant__ CUtensorMap tmap,
                 const float* __restrict__ bias,  // [co][pos]
                 float* __restrict__ out)         // [b][co][pos]
{
    __shared__ __align__(1024) uint8_t stg[NSTAGE][STAGE_BYTES]; // [W(TMA,SW128) | Xhi | Xlo]
    __shared__ uint64_t mbar[NSTAGE];
    __shared__ int xoffs[KTOT];
    __shared__ float sbias[64];

    int pos = blockIdx.x, y = pos >> 5, x = pos & 31;
    int tid = threadIdx.x, w = tid >> 5, lane = tid & 31;
    int g = lane >> 2, tq = lane & 3;
    int kw = w & 1;        // k16-chunk within 32-k tile
    int nh = w >> 1;       // n-tile group (0..3)

    for (int k = tid; k < KTOT; k += 256) {
        int ci = k / 9, rr = k - ci * 9, ki = rr / 3, kj = rr - ki * 3;
        int iy = y + ki - 1, ix = x + kj - 1;
        xoffs[k] = ((unsigned)iy < 32u && (unsigned)ix < 32u)
                     ? ((ci * 32 + iy) * 32 + ix) * 32 : -1;
    }
    if (tid < 64) sbias[tid] = bias[(size_t)tid * 1024 + pos];
    uint32_t mb0 = smem_u32(&mbar[0]);
    if (tid == 0) {
#pragma unroll
        for (int s = 0; s < NSTAGE; ++s)
            asm volatile("mbarrier.init.shared.b64 [%0], %1;" :: "r"(mb0 + 8 * s), "r"(1) : "memory");
    }
    __syncthreads();

    uint32_t stg_a = smem_u32(stg);

    // X staging indices
    int xarr = tid >> 7;                          // 0=hi, 1=lo
    int xk   = (tid >> 2) & 31;                   // k row
    int xch  = tid & 3;                           // 16B chunk in 64B row
    const __nv_bfloat16* xsrc_base = xarr ? g_xl : g_xh;

    auto issue = [&](int t, int s) {
        uint32_t ws_b = stg_a + (uint32_t)s * STAGE_BYTES;
        if (tid == 0) {
            uint32_t mb = mb0 + 8 * s;
            asm volatile("mbarrier.arrive.expect_tx.shared.b64 _, [%0], %1;"
                         :: "r"(mb), "r"(WS_BYTES) : "memory");
            asm volatile(
                "cp.async.bulk.tensor.2d.shared::cta.global.tile.mbarrier::complete_tx::bytes "
                "[%0], [%1, {%2, %3}], [%4];"
                :: "r"(ws_b), "l"(&tmap), "r"(t * KT), "r"(pos * 64), "r"(mb) : "memory");
        }
        int off = xoffs[t * KT + xk];
        const __nv_bfloat16* xsrc = xsrc_base + (off >= 0 ? off : 0) + xch * 8;
        uint32_t xdst = ws_b + WS_BYTES + (uint32_t)xarr * XH_BYTES
                        + (uint32_t)(xk * XR + xch * 8) * 2;
        CPA16(xdst, xsrc, off >= 0 ? 16 : 0);
    };

    float acc[2][2][4];
#pragma unroll
    for (int mt = 0; mt < 2; ++mt)
#pragma unroll
        for (int n = 0; n < 2; ++n)
#pragma unroll
            for (int c = 0; c < 4; ++c) acc[mt][n][c] = 0.f;

    issue(0, 0); CPA_COMMIT();
    issue(1, 1); CPA_COMMIT();

    // t-invariant fragment addresses
    int lrow = (kw * 16) + ((lane & 16) >> 1) + (lane & 7);
    int lcol = (lane & 8);
    uint32_t a_off[2];
#pragma unroll
    for (int mt = 0; mt < 2; ++mt)
        a_off[mt] = (uint32_t)(lrow * XR + mt * 16 + lcol) * 2 + WS_BYTES;
    int colb = (kw * 16 + 2 * tq) * 4;
    uint32_t b_off[2][2];
    int co_n[2];
#pragma unroll
    for (int n = 0; n < 2; ++n) {
        co_n[n] = (nh * 2 + n) * 8 + g;
#pragma unroll
        for (int ko = 0; ko < 2; ++ko)
            b_off[n][ko] = (uint32_t)co_n[n] * 128
                         + (uint32_t)((colb + ko * 32) ^ ((co_n[n] & 7) << 4));
    }

    for (int t = 0; t < NTILES; ++t) {
        int s = t - (t / NSTAGE) * NSTAGE;
        uint32_t sb_ = stg_a + (uint32_t)s * STAGE_BYTES;
        // W wait: warp 0 polls the mbarrier; entry barrier propagates
        if (w == 0) {
            uint32_t mb = mb0 + 8 * s;
            uint32_t ph = (t / NSTAGE) & 1;
            asm volatile(
                "{ .reg .pred P;\n\t"
                "WL%=: mbarrier.try_wait.parity.acquire.cta.shared::cta.b64 P, [%0], %1, 0x989680;\n\t"
                "@P bra WD%=;\n\t"
                "bra WL%=;\n\t"
                "WD%=: }"
                :: "r"(mb), "r"(ph) : "memory");
        }
        CPA_WAIT1();           // own X groups for tile t arrived
        __syncthreads();       // single barrier: visibility + WAR protection

        // ---- A frags: ldmatrix.trans from bf16 hi/lo tiles ----
        uint32_t ah[2][4], al[2][4];
#pragma unroll
        for (int mt = 0; mt < 2; ++mt) {
            uint32_t a_addr = sb_ + a_off[mt];
            LDSMT4(ah[mt], a_addr);
            LDSMT4(al[mt], a_addr + XH_BYTES);
        }

        // ---- per n-tile: B frags (convert-at-consume, SW128 swizzled rows) ----
#pragma unroll
        for (int n = 0; n < 2; ++n) {
            uint32_t bh[2], bl[2];
#pragma unroll
            for (int ko = 0; ko < 2; ++ko) {
                float2 f;
                asm volatile("ld.shared.v2.f32 {%0, %1}, [%2];"
                             : "=f"(f.x), "=f"(f.y) : "r"(sb_ + b_off[n][ko]));
                split_pair(f.x, f.y, bh[ko], bl[ko]);
            }
#pragma unroll
            for (int mt = 0; mt < 2; ++mt) {
                MMA16(acc[mt][n], ah[mt], bh);   // hi*hi
                MMA16(acc[mt][n], ah[mt], bl);   // hi*lo
                MMA16(acc[mt][n], al[mt], bh);   // lo*hi
            }
        }
        if (t + 2 < NTILES) issue(t + 2, (t + 2) - ((t + 2) / NSTAGE) * NSTAGE);
        CPA_COMMIT();          // unconditional: retires the final data groups
    }

    // ---- reduce across kw pairs via smem, then store ----
    __syncthreads();
    float* red = (float*)stg[0];
    if (kw == 1) {
        float* base = red + nh * 512;
#pragma unroll
        for (int mt = 0; mt < 2; ++mt)
#pragma unroll
            for (int n = 0; n < 2; ++n)
#pragma unroll
                for (int c = 0; c < 4; ++c)
                    base[((mt * 2 + n) * 4 + c) * 32 + lane] = acc[mt][n][c];
    }
    __syncthreads();
    if (kw == 0) {
        const float* base = red + nh * 512;
#pragma unroll
        for (int mt = 0; mt < 2; ++mt)
#pragma unroll
            for (int n = 0; n < 2; ++n) {
                int co0 = (nh * 2 + n) * 8 + 2 * tq;
#pragma unroll
                for (int c = 0; c < 4; ++c) {
                    float v = acc[mt][n][c] + base[((mt * 2 + n) * 4 + c) * 32 + lane];
                    int b  = mt * 16 + g + 8 * (c >> 1);
                    int co = co0 + (c & 1);
                    out[((size_t)b * 64 + co) * 1024 + pos] = v + sbias[co];
                }
            }
    }
}

typedef CUresult (*EncodeTiledFn)(
    CUtensorMap*, CUtensorMapDataType, cuuint32_t, void*,
    const cuuint64_t*, const cuuint64_t*, const cuuint32_t*, const cuuint32_t*,
    CUtensorMapInterleave, CUtensorMapSwizzle, CUtensorMapL2promotion,
    CUtensorMapFloatOOBfill);

extern "C" void kernel_launch(void* const* d_in, const int* in_sizes, int n_in,
                              void* d_out, int out_size) {
    const float* x    = (const float*)d_in[0];
    const float* wgt  = (const float*)d_in[1];
    const float* bias = (const float*)d_in[2];
    float* out = (float*)d_out;

    void* fn = nullptr;
    cudaDriverEntryPointQueryResult qr;
    cudaGetDriverEntryPoint("cuTensorMapEncodeTiled", &fn, cudaEnableDefault, &qr);
    CUtensorMap tmap;
    cuuint64_t dims[2]    = {576, 65536};
    cuuint64_t strides[1] = {576 * 4};
    cuuint32_t box[2]     = {32, 64};
    cuuint32_t es[2]      = {1, 1};
    ((EncodeTiledFn)fn)(&tmap, CU_TENSOR_MAP_DATA_TYPE_FLOAT32, 2, (void*)wgt,
                        dims, strides, box, es,
                        CU_TENSOR_MAP_INTERLEAVE_NONE, CU_TENSOR_MAP_SWIZZLE_128B,
                        CU_TENSOR_MAP_L2_PROMOTION_L2_128B,
                        CU_TENSOR_MAP_FLOAT_OOB_FILL_NONE);

    transpose_x_kernel<<<CIN * HW, 256>>>(x);
    local2d_mma<<<HW * HW, 256>>>(tmap, bias, out);
}

// round 11
// speedup vs baseline: 3.7294x; 1.0894x over previous
#include <cuda_runtime.h>
#include <cuda_bf16.h>
#include <cuda.h>
#include <cstdint>

#define CIN 64
#define COUT 64
#define HW 32
#define KTOT 576
#define KT 32
#define NTILES 18
#define XR 40                              // bf16 per X row (80B, ldmatrix conflict-free)

#define W_POS_BYTES 8192                   // 64 co x 128B (SW128)
#define W_ALL_BYTES 32768                  // 4 pos
#define X_ARR_BYTES 2560                   // 32 rows x 80B
#define X_POS_BYTES 5120                   // hi + lo
#define STAGE_BYTES 53248                  // W_ALL + 4*X_POS
#define OFF_VOFF   106496                  // 2 stages end
#define OFF_SBIAS  111104                  // voff: 1152 int
#define OFF_MBAR   112128                  // sbias: 256 float
#define SMEM_TOTAL 112144

// x as bf16 hi/lo, layout [ci][h][w][b] (b innermost, 64B rows)
__device__ __nv_bfloat16 g_xh[CIN * HW * HW * 32];
__device__ __nv_bfloat16 g_xl[CIN * HW * HW * 32];

__global__ void transpose_x_kernel(const float* __restrict__ x) {
    __shared__ float tile[32][33];
    int cih = blockIdx.x;
    int lane = threadIdx.x & 31;
    int grp  = threadIdx.x >> 5;
    const float* src = x + (size_t)cih * 32;
#pragma unroll
    for (int i = 0; i < 4; ++i) {
        int b = grp + 8 * i;
        tile[b][lane] = src[(size_t)b * 65536 + lane];
    }
    __syncthreads();
    size_t base = (size_t)cih * 1024;
#pragma unroll
    for (int i = 0; i < 4; ++i) {
        int w = grp + 8 * i;
        float v = tile[lane][w];
        __nv_bfloat16 h = __float2bfloat16(v);
        __nv_bfloat16 l = __float2bfloat16(v - __bfloat162float(h));
        g_xh[base + w * 32 + lane] = h;
        g_xl[base + w * 32 + lane] = l;
    }
}

__device__ __forceinline__ uint32_t smem_u32(const void* p) {
    uint32_t a;
    asm("{ .reg .u64 t; cvta.to.shared.u64 t, %1; cvt.u32.u64 %0, t; }" : "=r"(a) : "l"(p));
    return a;
}

// hi = top-16 truncation of pair (f0=low element), lo = bf16(f - hi) pair
__device__ __forceinline__ void split_pair(float f0, float f1, uint32_t& hi2, uint32_t& lo2) {
    asm("prmt.b32 %0, %1, %2, 0x7632;" : "=r"(hi2) : "r"(__float_as_uint(f0)), "r"(__float_as_uint(f1)));
    float h0 = __uint_as_float(__float_as_uint(f0) & 0xFFFF0000u);
    float h1 = __uint_as_float(__float_as_uint(f1) & 0xFFFF0000u);
    asm("cvt.rn.bf16x2.f32 %0, %1, %2;" : "=r"(lo2) : "f"(f1 - h1), "f"(f0 - h0));
}

#define MMA16(d, a, b) \
    asm volatile("mma.sync.aligned.m16n8k16.row.col.f32.bf16.bf16.f32 " \
        "{%0,%1,%2,%3}, {%4,%5,%6,%7}, {%8,%9}, {%0,%1,%2,%3};" \
        : "+f"(d[0]), "+f"(d[1]), "+f"(d[2]), "+f"(d[3]) \
        : "r"(a[0]), "r"(a[1]), "r"(a[2]), "r"(a[3]), "r"(b[0]), "r"(b[1]))

#define LDSMT4(r, a) \
    asm volatile("ldmatrix.sync.aligned.m8n8.x4.trans.shared.b16 {%0,%1,%2,%3}, [%4];" \
        : "=r"(r[0]), "=r"(r[1]), "=r"(r[2]), "=r"(r[3]) : "r"(a))

#define CPA16(dst, src, sz) \
    asm volatile("cp.async.cg.shared.global [%0], [%1], 16, %2;" \
        :: "r"(dst), "l"(src), "r"(sz) : "memory")
#define CPA_COMMIT() asm volatile("cp.async.commit_group;" ::: "memory")
#define CPA_WAIT1()  asm volatile("cp.async.wait_group 1;" ::: "memory")
#define CPA_WAIT0()  asm volatile("cp.async.wait_group 0;" ::: "memory")

__global__ __launch_bounds__(512, 2)
void local2d_mma(const __grid_constant__ CUtensorMap tmap,
                 const float* __restrict__ bias,  // [co][pos]
                 float* __restrict__ out)         // [b][co][pos]
{
    extern __shared__ __align__(1024) uint8_t dyn[];
    int*   voff  = (int*)(dyn + OFF_VOFF);    // [u=ci*3+ki][j=kj+pg] element offsets
    float* sbias = (float*)(dyn + OFF_SBIAS); // [pg][co]

    int tid = threadIdx.x;
    int pg = tid >> 7;                 // position within CTA (0..3)
    int ptid = tid & 127;
    int lane = tid & 31;
    int nh = ptid >> 5;                // n-tile group within position
    int g = lane >> 2, tq = lane & 3;

    int bx = blockIdx.x;
    int y = bx >> 3, x0 = (bx & 7) * 4;
    int pos0 = y * 32 + x0;

    // ---- voff table: [192 u][6 j] ----
    for (int idx = tid; idx < 1152; idx += 512) {
        int u = idx / 6, j = idx - u * 6;
        int ci = u / 3, ki = u - ci * 3;
        int iy = y + ki - 1, ix = x0 - 1 + j;
        voff[idx] = ((unsigned)iy < 32u && (unsigned)ix < 32u)
                      ? ((ci * 32 + iy) * 32 + ix) * 32 : -1;
    }
    if (tid < 256) sbias[tid] = bias[(size_t)(tid & 63) * 1024 + pos0 + (tid >> 6)];

    uint32_t dyn_a = smem_u32(dyn);
    uint32_t mb0 = dyn_a + OFF_MBAR;
    if (tid == 0) {
        asm volatile("mbarrier.init.shared.b64 [%0], %1;" :: "r"(mb0), "r"(1) : "memory");
        asm volatile("mbarrier.init.shared.b64 [%0], %1;" :: "r"(mb0 + 8), "r"(1) : "memory");
    }
    __syncthreads();

    // X staging constants (this thread stages one 16B chunk of hi and lo)
    int xrow = (ptid >> 2) & 31;
    int xch  = ptid & 3;

    auto issue = [&](int t) {
        int s = t & 1;
        uint32_t sbase = dyn_a + (uint32_t)s * STAGE_BYTES;
        if (tid == 0) {
            uint32_t mb = mb0 + 8 * s;
            asm volatile("mbarrier.arrive.expect_tx.shared.b64 _, [%0], %1;"
                         :: "r"(mb), "r"(W_ALL_BYTES) : "memory");
            asm volatile(
                "cp.async.bulk.tensor.2d.shared::cta.global.tile.mbarrier::complete_tx::bytes "
                "[%0], [%1, {%2, %3}], [%4];"
                :: "r"(sbase), "l"(&tmap), "r"(t * KT), "r"(pos0 * 64), "r"(mb) : "memory");
        }
        int K = t * KT + xrow;
        int u = (int)(((unsigned)K * 0xAAABu) >> 17);   // K/3
        int j = K - u * 3 + pg;
        int off = voff[u * 6 + j];
        const __nv_bfloat16* sh = g_xh + (off < 0 ? 0 : off) + xch * 8;
        const __nv_bfloat16* sl = g_xl + (off < 0 ? 0 : off) + xch * 8;
        int sz = off < 0 ? 0 : 16;
        uint32_t xb = sbase + W_ALL_BYTES + (uint32_t)pg * X_POS_BYTES
                      + (uint32_t)(xrow * XR + xch * 8) * 2;
        CPA16(xb, sh, sz);
        CPA16(xb + X_ARR_BYTES, sl, sz);
    };

    float acc[2][2][4];
#pragma unroll
    for (int mt = 0; mt < 2; ++mt)
#pragma unroll
        for (int n = 0; n < 2; ++n)
#pragma unroll
            for (int c = 0; c < 4; ++c) acc[mt][n][c] = 0.f;

    issue(0); CPA_COMMIT();
    issue(1); CPA_COMMIT();

    // t-invariant fragment offsets
    uint32_t a_off[2][2];    // [k16][mt], relative to X pos block (hi)
#pragma unroll
    for (int k16 = 0; k16 < 2; ++k16) {
        int lrow = k16 * 16 + ((lane & 16) >> 1) + (lane & 7);
#pragma unroll
        for (int mt = 0; mt < 2; ++mt)
            a_off[k16][mt] = (uint32_t)(lrow * XR + mt * 16 + (lane & 8)) * 2;
    }
    uint32_t b_off[2][2][2]; // [k16][n][ko], relative to W pos block
    int co_n[2];
#pragma unroll
    for (int n = 0; n < 2; ++n) {
        co_n[n] = (nh * 2 + n) * 8 + g;
#pragma unroll
        for (int k16 = 0; k16 < 2; ++k16)
#pragma unroll
            for (int ko = 0; ko < 2; ++ko)
                b_off[k16][n][ko] = (uint32_t)co_n[n] * 128
                    + (uint32_t)((((k16 * 16 + 2 * tq) * 4) + ko * 32) ^ ((co_n[n] & 7) << 4));
    }

    for (int t = 0; t < NTILES; ++t) {
        int s = t & 1;
        uint32_t sbase = dyn_a + (uint32_t)s * STAGE_BYTES;
        uint32_t sbW = sbase + (uint32_t)pg * W_POS_BYTES;
        uint32_t sbX = sbase + W_ALL_BYTES + (uint32_t)pg * X_POS_BYTES;

        if (tid < 32) {   // warp 0 polls TMA mbarrier
            uint32_t mb = mb0 + 8 * s;
            uint32_t ph = (t >> 1) & 1;
            asm volatile(
                "{ .reg .pred P;\n\t"
                "WL%=: mbarrier.try_wait.parity.acquire.cta.shared::cta.b64 P, [%0], %1, 0x989680;\n\t"
                "@P bra WD%=;\n\t"
                "bra WL%=;\n\t"
                "WD%=: }"
                :: "r"(mb), "r"(ph) : "memory");
        }
        CPA_WAIT1();
        __syncthreads();

#pragma unroll
        for (int k16 = 0; k16 < 2; ++k16) {
            uint32_t ah[2][4], al[2][4];
#pragma unroll
            for (int mt = 0; mt < 2; ++mt) {
                uint32_t a_addr = sbX + a_off[k16][mt];
                LDSMT4(ah[mt], a_addr);
                LDSMT4(al[mt], a_addr + X_ARR_BYTES);
            }
#pragma unroll
            for (int n = 0; n < 2; ++n) {
                uint32_t bh[2], bl[2];
#pragma unroll
                for (int ko = 0; ko < 2; ++ko) {
                    float2 f;
                    asm volatile("ld.shared.v2.f32 {%0, %1}, [%2];"
                                 : "=f"(f.x), "=f"(f.y) : "r"(sbW + b_off[k16][n][ko]));
                    split_pair(f.x, f.y, bh[ko], bl[ko]);
                }
#pragma unroll
                for (int mt = 0; mt < 2; ++mt) {
                    MMA16(acc[mt][n], ah[mt], bh);   // hi*hi
                    MMA16(acc[mt][n], ah[mt], bl);   // hi*lo
                    MMA16(acc[mt][n], al[mt], bh);   // lo*hi
                }
            }
        }
        __syncthreads();   // all reads of stage s done before refill
        if (t + 2 < NTILES) issue(t + 2);
        CPA_COMMIT();
    }

    // ---- epilogue: smem transpose to [b*64+co][pos4], coalesced STG.128 ----
    CPA_WAIT0();
    __syncthreads();
    float* ex = (float*)dyn;   // 32 KB
#pragma unroll
    for (int mt = 0; mt < 2; ++mt)
#pragma unroll
        for (int n = 0; n < 2; ++n)
#pragma unroll
            for (int c = 0; c < 4; ++c) {
                int b  = mt * 16 + ((c >> 1) << 3) + g;
                int co = (nh * 2 + n) * 8 + 2 * tq + (c & 1);
                ex[(b * 64 + co) * 4 + pg] = acc[mt][n][c] + sbias[pg * 64 + co];
            }
    __syncthreads();
#pragma unroll
    for (int i = 0; i < 4; ++i) {
        int bc = tid + 512 * i;
        float4 v = *(const float4*)(ex + bc * 4);
        *(float4*)(out + (size_t)bc * 1024 + pos0) = v;
    }
}

typedef CUresult (*EncodeTiledFn)(
    CUtensorMap*, CUtensorMapDataType, cuuint32_t, void*,
    const cuuint64_t*, const cuuint64_t*, const cuuint32_t*, const cuuint32_t*,
    CUtensorMapInterleave, CUtensorMapSwizzle, CUtensorMapL2promotion,
    CUtensorMapFloatOOBfill);

extern "C" void kernel_launch(void* const* d_in, const int* in_sizes, int n_in,
                              void* d_out, int out_size) {
    const float* x    = (const float*)d_in[0];
    const float* wgt  = (const float*)d_in[1];
    const float* bias = (const float*)d_in[2];
    float* out = (float*)d_out;

    void* fn = nullptr;
    cudaDriverEntryPointQueryResult qr;
    cudaGetDriverEntryPoint("cuTensorMapEncodeTiled", &fn, cudaEnableDefault, &qr);
    CUtensorMap tmap;
    cuuint64_t dims[2]    = {576, 65536};
    cuuint64_t strides[1] = {576 * 4};
    cuuint32_t box[2]     = {32, 256};     // 32 k x 256 rows (4 pos x 64 co)
    cuuint32_t es[2]      = {1, 1};
    ((EncodeTiledFn)fn)(&tmap, CU_TENSOR_MAP_DATA_TYPE_FLOAT32, 2, (void*)wgt,
                        dims, strides, box, es,
                        CU_TENSOR_MAP_INTERLEAVE_NONE, CU_TENSOR_MAP_SWIZZLE_128B,
                        CU_TENSOR_MAP_L2_PROMOTION_L2_128B,
                        CU_TENSOR_MAP_FLOAT_OOB_FILL_NONE);

    cudaFuncSetAttribute(local2d_mma, cudaFuncAttributeMaxDynamicSharedMemorySize, SMEM_TOTAL);
    transpose_x_kernel<<<CIN * HW, 256>>>(x);
    local2d_mma<<<256, 512, SMEM_TOTAL>>>(tmap, bias, out);
}